// round 6
// baseline (speedup 1.0000x reference)
#include <cuda_runtime.h>
#include <math.h>
#include <stdint.h>

#define Bn 64
#define Tn 2048
#define Dn 256
#define Un 256

// ---- scratch (device globals, no allocation) ----
__device__ float d_qp[Bn * Un];            // q_proj + W1_b + W2_b
__device__ float d_score[Bn * Tn];         // pre-softmax scores
__device__ float d_pmax[Bn * 16];          // per-score-block max
__device__ float d_psum[Bn * 16];          // per-score-block sum(exp(s - pmax))
__device__ float d_part[Bn * 32 * Dn];     // partial context sums
__device__ float d_W2t[Un * Dn];           // W2 transposed: [u][d]

// ================= helpers =================
__device__ __forceinline__ uint32_t smem_u32(const void* p) {
    uint32_t a;
    asm("{ .reg .u64 t; cvta.to.shared.u64 t, %1; cvt.u32.u64 %0, t; }" : "=r"(a) : "l"(p));
    return a;
}
__device__ __forceinline__ void cp_async16(uint32_t dst, const void* src) {
    asm volatile("cp.async.ca.shared.global [%0], [%1], 16;" :: "r"(dst), "l"(src) : "memory");
}
__device__ __forceinline__ void cp_commit() {
    asm volatile("cp.async.commit_group;" ::: "memory");
}
template <int N>
__device__ __forceinline__ void cp_wait() {
    asm volatile("cp.async.wait_group %0;" :: "n"(N) : "memory");
}
__device__ __forceinline__ void mma_tf32(float* c, const uint32_t* a, uint32_t b0, uint32_t b1) {
    asm volatile(
        "mma.sync.aligned.m16n8k8.row.col.f32.tf32.tf32.f32 "
        "{%0,%1,%2,%3}, {%4,%5,%6,%7}, {%8,%9}, {%0,%1,%2,%3};"
        : "+f"(c[0]), "+f"(c[1]), "+f"(c[2]), "+f"(c[3])
        : "r"(a[0]), "r"(a[1]), "r"(a[2]), "r"(a[3]), "r"(b0), "r"(b1));
}
static __device__ __forceinline__ float tanh_fast(float x) {
    float r;
    asm("tanh.approx.f32 %0, %1;" : "=f"(r) : "f"(x));
    return r;
}
__device__ __forceinline__ float warp_max(float v) {
#pragma unroll
    for (int o = 16; o > 0; o >>= 1) v = fmaxf(v, __shfl_xor_sync(0xffffffffu, v, o));
    return v;
}
__device__ __forceinline__ float warp_sum(float v) {
#pragma unroll
    for (int o = 16; o > 0; o >>= 1) v += __shfl_xor_sync(0xffffffffu, v, o);
    return v;
}

// ============================================================
// Kernel 0: prep — qproj (blocks 0..63) + W2 transpose (blocks 64..127)
// ============================================================
__global__ void prep_kernel(const float* __restrict__ query,
                            const float* __restrict__ W1w,
                            const float* __restrict__ W1b,
                            const float* __restrict__ W2w,
                            const float* __restrict__ W2b) {
    if (blockIdx.x < 64) {
        int b = blockIdx.x, u = threadIdx.x;
        __shared__ float qs[Dn];
        qs[u] = query[b * Dn + u];
        __syncthreads();
        float acc = 0.f;
#pragma unroll 8
        for (int d = 0; d < Dn; d++) acc = fmaf(qs[d], W1w[d * Un + u], acc);
        d_qp[b * Un + u] = acc + W1b[u] + W2b[u];
    } else {
        __shared__ float t[32][33];
        int tile = blockIdx.x - 64;
        int bx = (tile & 7) * 32, by = (tile >> 3) * 32;
        int x = threadIdx.x & 31, y = threadIdx.x >> 5;
#pragma unroll
        for (int i = 0; i < 32; i += 8) t[y + i][x] = W2w[(by + y + i) * Un + bx + x];
        __syncthreads();
#pragma unroll
        for (int i = 0; i < 32; i += 8) d_W2t[(bx + y + i) * Dn + by + x] = t[x][y + i];
    }
}

// ============================================================
// Kernel 2: mma.sync tf32 GEMM (128 x 256 x 256) + tanh + dot(Vw)
// 256 threads = 8 warps = 2 M-groups x 4 N-groups; warp tile 64x64.
// K chunks of 32, cp.async TRIPLE-buffered, stride-36 smem.
// Tail: fused per-block softmax partials (max, sum-exp).
// ============================================================
#define AS_STRIDE 36
#define A_ROWS 128
#define AS_FLOATS (A_ROWS * AS_STRIDE)   // 4608 per buffer
#define BS_FLOATS (256 * AS_STRIDE)      // 9216 per buffer
#define STG_FLOATS (AS_FLOATS + BS_FLOATS)
#define SC_SMEM (3 * STG_FLOATS * 4)     // 165888 B

__global__ __launch_bounds__(256, 1)
void score_kernel(const float* __restrict__ values,
                  const float* __restrict__ Vw,
                  const float* __restrict__ Vb) {
    extern __shared__ __align__(16) char dsm[];
    float* stg = (float*)dsm;    // 3 stages of [A(4608) | B(9216)]
    __shared__ float qs[Un];
    __shared__ float vs[Un];
    __shared__ float sp[A_ROWS * 4];
    __shared__ float rmax[4], rsum[4];

    const int tid = threadIdx.x;
    const int wid = tid >> 5;
    const int lane = tid & 31;
    const int g = lane >> 2;       // 0..7
    const int tg = lane & 3;       // 0..3
    const int mw = wid >> 2;       // 0..1  (64-row group)
    const int nw = wid & 3;        // 0..3  (64-col group)
    const int r0 = blockIdx.x * A_ROWS;
    const int b = r0 >> 11;

    qs[tid] = d_qp[b * Un + tid];
    vs[tid] = Vw[tid];

    const uint32_t st_base = smem_u32(stg);

    auto issue_chunk = [&](int c, int buf) {
        const int kc = c * 32;
        const uint32_t ab = st_base + (buf * STG_FLOATS) * 4;
        const uint32_t bb = ab + AS_FLOATS * 4;
        const float* agp = values + (size_t)r0 * Dn + kc;
#pragma unroll
        for (int it = 0; it < 4; it++) {
            int s = tid + it * 256;          // 1024 float4 slots
            int row = s >> 3, kq = s & 7;
            cp_async16(ab + (row * AS_STRIDE + kq * 4) * 4, agp + row * Dn + kq * 4);
        }
#pragma unroll
        for (int it = 0; it < 8; it++) {
            int s = tid + it * 256;          // 2048 float4 slots
            int row = s >> 3, kq = s & 7;
            cp_async16(bb + (row * AS_STRIDE + kq * 4) * 4, d_W2t + row * Dn + kc + kq * 4);
        }
        cp_commit();
    };

    float acc[4][8][4];   // 128 regs
#pragma unroll
    for (int i = 0; i < 4; i++)
#pragma unroll
        for (int j = 0; j < 8; j++)
#pragma unroll
            for (int q = 0; q < 4; q++) acc[i][j][q] = 0.f;

    issue_chunk(0, 0);
    issue_chunk(1, 1);

#pragma unroll 1
    for (int c = 0; c < 8; c++) {
        if (c < 7) cp_wait<1>(); else cp_wait<0>();
        __syncthreads();                 // chunk c resident; previous readers done
        if (c + 2 < 8) issue_chunk(c + 2, (c + 2) % 3);

        const int buf = c % 3;
        const uint32_t* Au = (const uint32_t*)(stg + buf * STG_FLOATS);
        const uint32_t* Bu = Au + AS_FLOATS;

#pragma unroll
        for (int k8 = 0; k8 < 4; k8++) {
            const int kb = k8 * 8;
            uint32_t afr[4][4];
#pragma unroll
            for (int i = 0; i < 4; i++) {
                int row = mw * 64 + i * 16 + g;
                afr[i][0] = Au[row * AS_STRIDE + kb + tg];
                afr[i][1] = Au[(row + 8) * AS_STRIDE + kb + tg];
                afr[i][2] = Au[row * AS_STRIDE + kb + tg + 4];
                afr[i][3] = Au[(row + 8) * AS_STRIDE + kb + tg + 4];
            }
#pragma unroll
            for (int j = 0; j < 8; j++) {
                int urow = nw * 64 + j * 8 + g;
                uint32_t b0 = Bu[urow * AS_STRIDE + kb + tg];
                uint32_t b1 = Bu[urow * AS_STRIDE + kb + tg + 4];
#pragma unroll
                for (int i = 0; i < 4; i++)
                    mma_tf32(acc[i][j], afr[i], b0, b1);
            }
        }
    }

    // ---- epilogue: p[row] = sum_u tanh(acc + qs[u]) * vs[u] ----
    float p[4][2];
#pragma unroll
    for (int i = 0; i < 4; i++) { p[i][0] = 0.f; p[i][1] = 0.f; }

#pragma unroll
    for (int j = 0; j < 8; j++) {
        int u0 = nw * 64 + j * 8 + 2 * tg;
        int u1 = u0 + 1;
        float q0 = qs[u0], q1 = qs[u1], v0 = vs[u0], v1 = vs[u1];
#pragma unroll
        for (int i = 0; i < 4; i++) {
            p[i][0] = fmaf(tanh_fast(acc[i][j][0] + q0), v0, p[i][0]);
            p[i][0] = fmaf(tanh_fast(acc[i][j][1] + q1), v1, p[i][0]);
            p[i][1] = fmaf(tanh_fast(acc[i][j][2] + q0), v0, p[i][1]);
            p[i][1] = fmaf(tanh_fast(acc[i][j][3] + q1), v1, p[i][1]);
        }
    }
#pragma unroll
    for (int off = 1; off < 4; off <<= 1)
#pragma unroll
        for (int i = 0; i < 4; i++) {
            p[i][0] += __shfl_xor_sync(0xffffffffu, p[i][0], off);
            p[i][1] += __shfl_xor_sync(0xffffffffu, p[i][1], off);
        }
    if (tg == 0) {
#pragma unroll
        for (int i = 0; i < 4; i++) {
            sp[(mw * 64 + i * 16 + g) * 4 + nw] = p[i][0];
            sp[(mw * 64 + i * 16 + g + 8) * 4 + nw] = p[i][1];
        }
    }
    __syncthreads();

    // ---- final score + fused per-block softmax partials (warps 0..3) ----
    float s = 0.f;
    if (tid < A_ROWS) {
        s = sp[tid * 4] + sp[tid * 4 + 1] + sp[tid * 4 + 2] + sp[tid * 4 + 3] + Vb[0];
        d_score[r0 + tid] = s;
        float m = warp_max(s);
        if (lane == 0) rmax[wid] = m;
    }
    __syncthreads();
    if (tid < A_ROWS) {
        float bm = fmaxf(fmaxf(rmax[0], rmax[1]), fmaxf(rmax[2], rmax[3]));
        float e = expf(s - bm);
        float se = warp_sum(e);
        if (lane == 0) rsum[wid] = se;
        if (tid == 0) d_pmax[blockIdx.x] = bm;
    }
    __syncthreads();
    if (tid == 0) d_psum[blockIdx.x] = rsum[0] + rsum[1] + rsum[2] + rsum[3];
}

// ============================================================
// Kernel 4: weights + partial context (grid = B*32, 64-t chunks)
// warp 0 combines the 16 per-block partials inline (no stats kernel).
// ============================================================
__global__ void weights_ctx_kernel(const float* __restrict__ values,
                                   float* __restrict__ out) {
    int b = blockIdx.x >> 5;
    int ch = blockIdx.x & 31;
    int tid = threadIdx.x;
    __shared__ float sw[64];
    __shared__ float4 red[256];
    __shared__ float s_mv, s_den;

    if (tid < 32) {
        float m = (tid < 16) ? d_pmax[b * 16 + tid] : -1e30f;
        float sN = (tid < 16) ? d_psum[b * 16 + tid] : 0.f;
        float mv = warp_max(m);
        float den = warp_sum(sN * expf(m - mv));
        if (tid == 0) { s_mv = mv; s_den = den; }
    }
    __syncthreads();

    if (tid < 64) {
        int t = ch * 64 + tid;
        float w = expf(d_score[b * Tn + t] - s_mv) / s_den;
        out[Bn * Dn + b * Tn + t] = w;
        sw[tid] = w;
    }
    __syncthreads();

    int rg = tid >> 6, dg = tid & 63;      // 4 row groups x 16 rows
    const float4* vp = (const float4*)(values + (size_t)(b * Tn + ch * 64 + rg * 16) * Dn) + dg;
    float4 acc = make_float4(0.f, 0.f, 0.f, 0.f);
#pragma unroll 8
    for (int tt = 0; tt < 16; tt++) {
        float w = sw[rg * 16 + tt];
        float4 v = vp[(size_t)tt * 64];
        acc.x = fmaf(w, v.x, acc.x);
        acc.y = fmaf(w, v.y, acc.y);
        acc.z = fmaf(w, v.z, acc.z);
        acc.w = fmaf(w, v.w, acc.w);
    }
    red[tid] = acc;
    __syncthreads();
    if (tid < 64) {
        float4 a = red[tid], b1 = red[64 + tid], c = red[128 + tid], d = red[192 + tid];
        a.x += b1.x + c.x + d.x;
        a.y += b1.y + c.y + d.y;
        a.z += b1.z + c.z + d.z;
        a.w += b1.w + c.w + d.w;
        ((float4*)(d_part + (b * 32 + ch) * Dn))[tid] = a;
    }
}

// ============================================================
// Kernel 5: reduce partial contexts -> context_vector
// ============================================================
__global__ void reduce_ctx_kernel(float* __restrict__ out) {
    int b = blockIdx.x, d = threadIdx.x;
    float acc = 0.f;
#pragma unroll
    for (int c = 0; c < 32; c++) acc += d_part[(b * 32 + c) * Dn + d];
    out[b * Dn + d] = acc;
}

// ============================================================
extern "C" void kernel_launch(void* const* d_in, const int* in_sizes, int n_in,
                              void* d_out, int out_size) {
    const float* query = (const float*)d_in[0];
    const float* values = (const float*)d_in[1];
    const float* W1w = (const float*)d_in[2];
    const float* W1b = (const float*)d_in[3];
    const float* W2w = (const float*)d_in[4];
    const float* W2b = (const float*)d_in[5];
    const float* Vw  = (const float*)d_in[6];
    const float* Vb  = (const float*)d_in[7];
    float* out = (float*)d_out;

    static int smem_set = 0;
    if (!smem_set) {
        cudaFuncSetAttribute(score_kernel, cudaFuncAttributeMaxDynamicSharedMemorySize, SC_SMEM);
        smem_set = 1;
    }

    prep_kernel<<<128, 256>>>(query, W1w, W1b, W2w, W2b);
    score_kernel<<<(Bn * Tn) / A_ROWS, 256, SC_SMEM>>>(values, Vw, Vb);
    weights_ctx_kernel<<<Bn * 32, 256>>>(values, out);
    reduce_ctx_kernel<<<Bn, 256>>>(out);
}

// round 7
// speedup vs baseline: 1.4767x; 1.4767x over previous
#include <cuda_runtime.h>
#include <math.h>
#include <stdint.h>

#define Bn 64
#define Tn 2048
#define Dn 256
#define Un 256

// ---- scratch (device globals, no allocation) ----
__device__ float d_qp[Bn * Un];            // q_proj + W1_b + W2_b
__device__ float d_score[Bn * Tn];         // pre-softmax scores
__device__ float d_pmax[Bn * 16];          // per-score-block max
__device__ float d_psum[Bn * 16];          // per-score-block sum(exp(s - pmax))
__device__ float d_part[Bn * 32 * Dn];     // partial context sums
__device__ float d_W2t[Un * Dn];           // W2 transposed: [u][d]

// ================= helpers =================
__device__ __forceinline__ uint32_t smem_u32(const void* p) {
    uint32_t a;
    asm("{ .reg .u64 t; cvta.to.shared.u64 t, %1; cvt.u32.u64 %0, t; }" : "=r"(a) : "l"(p));
    return a;
}
__device__ __forceinline__ void cp_async16(uint32_t dst, const void* src) {
    asm volatile("cp.async.ca.shared.global [%0], [%1], 16;" :: "r"(dst), "l"(src) : "memory");
}
__device__ __forceinline__ void cp_commit() {
    asm volatile("cp.async.commit_group;" ::: "memory");
}
template <int N>
__device__ __forceinline__ void cp_wait() {
    asm volatile("cp.async.wait_group %0;" :: "n"(N) : "memory");
}
__device__ __forceinline__ void mma_tf32(float* c, const uint32_t* a, uint32_t b0, uint32_t b1) {
    asm volatile(
        "mma.sync.aligned.m16n8k8.row.col.f32.tf32.tf32.f32 "
        "{%0,%1,%2,%3}, {%4,%5,%6,%7}, {%8,%9}, {%0,%1,%2,%3};"
        : "+f"(c[0]), "+f"(c[1]), "+f"(c[2]), "+f"(c[3])
        : "r"(a[0]), "r"(a[1]), "r"(a[2]), "r"(a[3]), "r"(b0), "r"(b1));
}
static __device__ __forceinline__ float tanh_fast(float x) {
    float r;
    asm("tanh.approx.f32 %0, %1;" : "=f"(r) : "f"(x));
    return r;
}
__device__ __forceinline__ float warp_max(float v) {
#pragma unroll
    for (int o = 16; o > 0; o >>= 1) v = fmaxf(v, __shfl_xor_sync(0xffffffffu, v, o));
    return v;
}
__device__ __forceinline__ float warp_sum(float v) {
#pragma unroll
    for (int o = 16; o > 0; o >>= 1) v += __shfl_xor_sync(0xffffffffu, v, o);
    return v;
}

// ============================================================
// Kernel 0: prep — qproj (blocks 0..63) + W2 transpose (blocks 64..127)
// ============================================================
__global__ void prep_kernel(const float* __restrict__ query,
                            const float* __restrict__ W1w,
                            const float* __restrict__ W1b,
                            const float* __restrict__ W2w,
                            const float* __restrict__ W2b) {
    if (blockIdx.x < 64) {
        int b = blockIdx.x, u = threadIdx.x;
        __shared__ float qs[Dn];
        qs[u] = query[b * Dn + u];
        __syncthreads();
        float acc = 0.f;
#pragma unroll 8
        for (int d = 0; d < Dn; d++) acc = fmaf(qs[d], W1w[d * Un + u], acc);
        d_qp[b * Un + u] = acc + W1b[u] + W2b[u];
    } else {
        __shared__ float t[32][33];
        int tile = blockIdx.x - 64;
        int bx = (tile & 7) * 32, by = (tile >> 3) * 32;
        int x = threadIdx.x & 31, y = threadIdx.x >> 5;
#pragma unroll
        for (int i = 0; i < 32; i += 8) t[y + i][x] = W2w[(by + y + i) * Un + bx + x];
        __syncthreads();
#pragma unroll
        for (int i = 0; i < 32; i += 8) d_W2t[(bx + y + i) * Dn + by + x] = t[x][y + i];
    }
}

// ============================================================
// Kernel 2: mma.sync tf32 GEMM (128 x 256 x 256) + tanh + dot(Vw)
// EXACT R4 mainloop: 8 warps = 2 M-groups x 4 N-groups, warp tile 64x64,
// K chunks of 32, cp.async double-buffered, stride-36 smem.
// Tail: fused per-block softmax partials (max, sum-exp).
// ============================================================
#define AS_STRIDE 36
#define A_ROWS 128
#define AS_FLOATS (A_ROWS * AS_STRIDE)   // 4608 per buffer
#define BS_FLOATS (256 * AS_STRIDE)      // 9216 per buffer
#define SC_SMEM ((2 * AS_FLOATS + 2 * BS_FLOATS) * 4)   // 110592 B

__global__ __launch_bounds__(256, 1)
void score_kernel(const float* __restrict__ values,
                  const float* __restrict__ Vw,
                  const float* __restrict__ Vb) {
    extern __shared__ __align__(16) char dsm[];
    float* Asf = (float*)dsm;                       // 2 x 4608
    float* Bsf = (float*)dsm + 2 * AS_FLOATS;       // 2 x 9216
    __shared__ float qs[Un];
    __shared__ float vs[Un];
    __shared__ float sp[A_ROWS * 4];
    __shared__ float rmax[4], rsum[4];

    const int tid = threadIdx.x;
    const int wid = tid >> 5;
    const int lane = tid & 31;
    const int g = lane >> 2;       // 0..7
    const int tg = lane & 3;       // 0..3
    const int mw = wid >> 2;       // 0..1  (row half)
    const int nw = wid & 3;        // 0..3  (col quarter)
    const int r0 = blockIdx.x * A_ROWS;
    const int b = r0 >> 11;

    qs[tid] = d_qp[b * Un + tid];
    vs[tid] = Vw[tid];

    const uint32_t as_base = smem_u32(Asf);
    const uint32_t bs_base = smem_u32(Bsf);

    auto issue_chunk = [&](int c, int buf) {
        const int kc = c * 32;
        const float* agp = values + (size_t)r0 * Dn + kc;
#pragma unroll
        for (int it = 0; it < 4; it++) {
            int s = tid + it * 256;          // 1024 float4 slots
            int row = s >> 3, kq = s & 7;
            uint32_t dst = as_base + (buf * AS_FLOATS + row * AS_STRIDE + kq * 4) * 4;
            cp_async16(dst, agp + row * Dn + kq * 4);
        }
#pragma unroll
        for (int it = 0; it < 8; it++) {
            int s = tid + it * 256;          // 2048 float4 slots
            int row = s >> 3, kq = s & 7;
            uint32_t dst = bs_base + (buf * BS_FLOATS + row * AS_STRIDE + kq * 4) * 4;
            cp_async16(dst, d_W2t + row * Dn + kc + kq * 4);
        }
        cp_commit();
    };

    float acc[4][8][4];   // [m_tile][n_tile][c-frag] = 128 regs
#pragma unroll
    for (int i = 0; i < 4; i++)
#pragma unroll
        for (int j = 0; j < 8; j++)
#pragma unroll
            for (int q = 0; q < 4; q++) acc[i][j][q] = 0.f;

    issue_chunk(0, 0);

#pragma unroll 1
    for (int c = 0; c < 8; c++) {
        const int buf = c & 1;
        if (c < 7) issue_chunk(c + 1, buf ^ 1);
        if (c < 7) cp_wait<1>(); else cp_wait<0>();
        __syncthreads();

        const uint32_t* Au = (const uint32_t*)(Asf + buf * AS_FLOATS);
        const uint32_t* Bu = (const uint32_t*)(Bsf + buf * BS_FLOATS);

#pragma unroll
        for (int k8 = 0; k8 < 4; k8++) {
            const int kb = k8 * 8;
            uint32_t afr[4][4];
#pragma unroll
            for (int i = 0; i < 4; i++) {
                int row = mw * 64 + i * 16 + g;
                afr[i][0] = Au[row * AS_STRIDE + kb + tg];
                afr[i][1] = Au[(row + 8) * AS_STRIDE + kb + tg];
                afr[i][2] = Au[row * AS_STRIDE + kb + tg + 4];
                afr[i][3] = Au[(row + 8) * AS_STRIDE + kb + tg + 4];
            }
#pragma unroll
            for (int j = 0; j < 8; j++) {
                int urow = nw * 64 + j * 8 + g;
                uint32_t b0 = Bu[urow * AS_STRIDE + kb + tg];
                uint32_t b1 = Bu[urow * AS_STRIDE + kb + tg + 4];
#pragma unroll
                for (int i = 0; i < 4; i++)
                    mma_tf32(acc[i][j], afr[i], b0, b1);
            }
        }
        __syncthreads();
    }

    // ---- epilogue: p[row] = sum_u tanh(acc + qs[u]) * vs[u] ----
    float p[4][2];
#pragma unroll
    for (int i = 0; i < 4; i++) { p[i][0] = 0.f; p[i][1] = 0.f; }

#pragma unroll
    for (int j = 0; j < 8; j++) {
        int u0 = nw * 64 + j * 8 + 2 * tg;
        int u1 = u0 + 1;
        float q0 = qs[u0], q1 = qs[u1], v0 = vs[u0], v1 = vs[u1];
#pragma unroll
        for (int i = 0; i < 4; i++) {
            p[i][0] = fmaf(tanh_fast(acc[i][j][0] + q0), v0, p[i][0]);
            p[i][0] = fmaf(tanh_fast(acc[i][j][1] + q1), v1, p[i][0]);
            p[i][1] = fmaf(tanh_fast(acc[i][j][2] + q0), v0, p[i][1]);
            p[i][1] = fmaf(tanh_fast(acc[i][j][3] + q1), v1, p[i][1]);
        }
    }
#pragma unroll
    for (int off = 1; off < 4; off <<= 1)
#pragma unroll
        for (int i = 0; i < 4; i++) {
            p[i][0] += __shfl_xor_sync(0xffffffffu, p[i][0], off);
            p[i][1] += __shfl_xor_sync(0xffffffffu, p[i][1], off);
        }
    if (tg == 0) {
#pragma unroll
        for (int i = 0; i < 4; i++) {
            sp[(mw * 64 + i * 16 + g) * 4 + nw] = p[i][0];
            sp[(mw * 64 + i * 16 + g + 8) * 4 + nw] = p[i][1];
        }
    }
    __syncthreads();

    // ---- final score + fused per-block softmax partials (warps 0..3) ----
    float s = 0.f;
    if (tid < A_ROWS) {
        s = sp[tid * 4] + sp[tid * 4 + 1] + sp[tid * 4 + 2] + sp[tid * 4 + 3] + Vb[0];
        d_score[r0 + tid] = s;
        float m = warp_max(s);
        if (lane == 0) rmax[wid] = m;
    }
    __syncthreads();
    if (tid < A_ROWS) {
        float bm = fmaxf(fmaxf(rmax[0], rmax[1]), fmaxf(rmax[2], rmax[3]));
        float e = expf(s - bm);
        float se = warp_sum(e);
        if (lane == 0) rsum[wid] = se;
        if (tid == 0) d_pmax[blockIdx.x] = bm;
    }
    __syncthreads();
    if (tid == 0) d_psum[blockIdx.x] = rsum[0] + rsum[1] + rsum[2] + rsum[3];
}

// ============================================================
// Kernel 4: weights + partial context (grid = B*32, 64-t chunks)
// warp 0 combines the 16 per-block partials inline (no stats kernel).
// ============================================================
__global__ void weights_ctx_kernel(const float* __restrict__ values,
                                   float* __restrict__ out) {
    int b = blockIdx.x >> 5;
    int ch = blockIdx.x & 31;
    int tid = threadIdx.x;
    __shared__ float sw[64];
    __shared__ float4 red[256];
    __shared__ float s_mv, s_den;

    if (tid < 32) {
        float m = (tid < 16) ? d_pmax[b * 16 + tid] : -1e30f;
        float sN = (tid < 16) ? d_psum[b * 16 + tid] : 0.f;
        float mv = warp_max(m);
        float den = warp_sum(sN * expf(m - mv));
        if (tid == 0) { s_mv = mv; s_den = den; }
    }
    __syncthreads();

    if (tid < 64) {
        int t = ch * 64 + tid;
        float w = expf(d_score[b * Tn + t] - s_mv) / s_den;
        out[Bn * Dn + b * Tn + t] = w;
        sw[tid] = w;
    }
    __syncthreads();

    int rg = tid >> 6, dg = tid & 63;      // 4 row groups x 16 rows
    const float4* vp = (const float4*)(values + (size_t)(b * Tn + ch * 64 + rg * 16) * Dn) + dg;
    float4 acc = make_float4(0.f, 0.f, 0.f, 0.f);
#pragma unroll 8
    for (int tt = 0; tt < 16; tt++) {
        float w = sw[rg * 16 + tt];
        float4 v = vp[(size_t)tt * 64];
        acc.x = fmaf(w, v.x, acc.x);
        acc.y = fmaf(w, v.y, acc.y);
        acc.z = fmaf(w, v.z, acc.z);
        acc.w = fmaf(w, v.w, acc.w);
    }
    red[tid] = acc;
    __syncthreads();
    if (tid < 64) {
        float4 a = red[tid], b1 = red[64 + tid], c = red[128 + tid], d = red[192 + tid];
        a.x += b1.x + c.x + d.x;
        a.y += b1.y + c.y + d.y;
        a.z += b1.z + c.z + d.z;
        a.w += b1.w + c.w + d.w;
        ((float4*)(d_part + (b * 32 + ch) * Dn))[tid] = a;
    }
}

// ============================================================
// Kernel 5: reduce partial contexts -> context_vector
// 256 threads: (cgroup 0..3) x (float4 dg 0..63), 8 partials each.
// ============================================================
__global__ void reduce_ctx_kernel(float* __restrict__ out) {
    int b = blockIdx.x, tid = threadIdx.x;
    int cg = tid >> 6, dg = tid & 63;
    __shared__ float4 red[256];
    float4 acc = make_float4(0.f, 0.f, 0.f, 0.f);
#pragma unroll
    for (int c = 0; c < 8; c++) {
        float4 v = ((const float4*)(d_part + (b * 32 + cg * 8 + c) * Dn))[dg];
        acc.x += v.x; acc.y += v.y; acc.z += v.z; acc.w += v.w;
    }
    red[tid] = acc;
    __syncthreads();
    if (tid < 64) {
        float4 a = red[tid], b1 = red[64 + tid], c = red[128 + tid], d = red[192 + tid];
        a.x += b1.x + c.x + d.x;
        a.y += b1.y + c.y + d.y;
        a.z += b1.z + c.z + d.z;
        a.w += b1.w + c.w + d.w;
        ((float4*)(out + b * Dn))[tid] = a;
    }
}

// ============================================================
extern "C" void kernel_launch(void* const* d_in, const int* in_sizes, int n_in,
                              void* d_out, int out_size) {
    const float* query = (const float*)d_in[0];
    const float* values = (const float*)d_in[1];
    const float* W1w = (const float*)d_in[2];
    const float* W1b = (const float*)d_in[3];
    const float* W2w = (const float*)d_in[4];
    const float* W2b = (const float*)d_in[5];
    const float* Vw  = (const float*)d_in[6];
    const float* Vb  = (const float*)d_in[7];
    float* out = (float*)d_out;

    static int smem_set = 0;
    if (!smem_set) {
        cudaFuncSetAttribute(score_kernel, cudaFuncAttributeMaxDynamicSharedMemorySize, SC_SMEM);
        smem_set = 1;
    }

    prep_kernel<<<128, 256>>>(query, W1w, W1b, W2w, W2b);
    score_kernel<<<(Bn * Tn) / A_ROWS, 256, SC_SMEM>>>(values, Vw, Vb);
    weights_ctx_kernel<<<Bn * 32, 256>>>(values, out);
    reduce_ctx_kernel<<<Bn, 256>>>(out);
}